// round 17
// baseline (speedup 1.0000x reference)
#include <cuda_runtime.h>
#include <cstdint>

// Shapes (fixed):
//   log_probs: (128, 64) f32 | ref: (256, 128) i32 | hyp: (256, 128, 64) i32
#define NBATCH 128
#define NSAMP  64
#define NSEQ   (NBATCH * NSAMP)   // 8192
#define RLEN   256
#define HLEN   256
#define SYMS   1024               // tokens in [0,1000)
#define TPD    4                  // token prefetch ring depth
#define CH     16                 // carry hand-off chunk (bits per packed word)
#define NLC    (HLEN / CH)        // 16 active chunks per lane
#define NCHUNK (NLC + 3)          // 19 chunk-times (+3 skew for 4 lanes)

typedef unsigned long long ull;

__device__ double   d_partial[NBATCH];
__device__ unsigned d_ticket;      // zero at start; winner resets each run

// 32-bit x2 / pack on the FMA pipe (single IMADs — unlike the failed 64-bit mad)
__device__ __forceinline__ unsigned mul2(unsigned x) {
    unsigned r; asm("mul.lo.u32 %0, %1, 2;" : "=r"(r) : "r"(x)); return r;
}
__device__ __forceinline__ unsigned mad2(unsigned x, unsigned c) {
    unsigned r; asm("mad.lo.u32 %0, %1, 2, %2;" : "=r"(r) : "r"(x), "r"(c)); return r;
}

// ---------------------------------------------------------------------------
// Quad-split Myers: lane w (0..3, width-4 shuffle group) owns ref word w,
// runs w chunk-times behind lane w-1. Carry hand-off once per CH steps via
// one width-4 shuffle (never on the per-step chain). All carry plumbing is
// IMAD-form (fma pipe): pack pw=pw*2+po, MSB-extract umulhi(pw,2), advance
// pw*=2. Warm-up needs no sentinel: pre-start chunks chew wrapped real tokens
// (ring indices contiguous mod 256) and state+score reset at T==w. EOS needs
// no per-step detection: score accumulates only while hh < hlen (precomputed).
// Tail garbage is harmless: finished lanes' carries are never consumed, score
// is masked. Lane bsel's word carries the score bit.
// ---------------------------------------------------------------------------
template<bool TOP>
__device__ __forceinline__ int quad_run(const ull* __restrict__ sPeq,
                                        const int* __restrict__ hyp,
                                        int n, int w, int pm, int hlen) {
    ull Pv = ~0ull, Mv = 0ull;
    unsigned pw_prod = 0u, mw_prod = 0u;
    int score = 0;
    int hh = -CH * w;                    // unwrapped step index of this lane

    // prime token ring at wrapped indices (contiguous mod 256 forever)
    int toks[TPD];
    int tcur = hyp[(size_t)(hh & (HLEN - 1)) * NSEQ + n];
    #pragma unroll
    for (int k = 0; k < TPD; ++k)
        toks[k] = hyp[(size_t)((hh + 1 + k) & (HLEN - 1)) * NSEQ + n];
    ull E = sPeq[(tcur << 2) + w];

    #pragma unroll 1
    for (int T = 0; T < NCHUNK; ++T) {
        // chunk-boundary exchange: lane w gets lane w-1's last-chunk carries
        unsigned pw_in = __shfl_up_sync(0xffffffffu, pw_prod, 1, 4);
        unsigned mw_in = __shfl_up_sync(0xffffffffu, mw_prod, 1, 4);
        // MSB-align: producer packed step0 at bit CH-1
        unsigned pw_use = (w == 0) ? (0xFFFFu << (32 - CH)) : (pw_in << (32 - CH));
        unsigned mw_use = (w == 0) ? 0u                     : (mw_in << (32 - CH));
        pw_prod = 0u; mw_prod = 0u;
        if (T == w) { Pv = ~0ull; Mv = 0ull; score = 0; }  // wipe warm-up garbage

        #pragma unroll
        for (int j = 0; j < CH; ++j) {
            const int t1 = toks[0];
            ull N = sPeq[(t1 << 2) + w];

            // ring rotate + refill (renamed under full unroll); wrap is safe:
            // out-of-range steps only feed wiped/masked state
            #pragma unroll
            for (int k = 0; k < TPD - 1; ++k) toks[k] = toks[k + 1];
            toks[TPD - 1] = hyp[(size_t)((hh + 1 + TPD) & (HLEN - 1)) * NSEQ + n];

            // carry-ins: MSB extract + advance, all on the fma pipe
            ull phin = (ull)__umulhi(pw_use, 2u);
            ull mhin = (ull)__umulhi(mw_use, 2u);
            pw_use = mul2(pw_use);
            mw_use = mul2(mw_use);

            ull Eq = E;
            ull Xv = Eq | Mv;
            Eq |= mhin;
            ull Xh = (((Eq & Pv) + Pv) ^ Pv) | Eq;
            ull Ph = Mv | ~(Xh | Pv);
            ull Mh = Pv & Xh;
            unsigned po = (unsigned)(Ph >> 63);
            unsigned mo = (unsigned)(Mh >> 63);
            pw_prod = mad2(pw_prod, po);         // pack carry-outs (fma pipe)
            mw_prod = mad2(mw_prod, mo);

            int d;
            if (TOP) d = (int)po - (int)mo;      // pm==63 fast path
            else     d = (int)((Ph >> pm) & 1ull) - (int)((Mh >> pm) & 1ull);
            score += ((unsigned)hh < (unsigned)hlen) ? d : 0;  // warm-up/tail/EOS mask

            Ph = (Ph << 1) | phin;
            Mh = (Mh << 1) | mhin;
            Pv = Mh | ~(Xv | Ph);
            Mv = Ph & Xv;

            E = N;
            ++hh;
        }
    }
    return score;
}

// ---------------------------------------------------------------------------
// Fused kernel: block b = batch row b, 256 threads = 64 samples x 4 lanes.
// 8 warps/block -> 2 warps on every SMSP of 128 SMs.
// ---------------------------------------------------------------------------
__global__ void __launch_bounds__(256, 1)
mer_loss_kernel(const int* __restrict__ hyp,
                const int* __restrict__ ref,
                const float* __restrict__ logp,
                float* __restrict__ out) {
    __shared__ ull    sPeq[SYMS * 4];   // 32 KB bitmask table
    __shared__ int    sMinEos;
    __shared__ int    sHlen[NSAMP];
    __shared__ float  sEr[NSAMP];
    __shared__ bool   sLast;
    __shared__ double sSum[NBATCH];

    const int b   = blockIdx.x;
    const int tid = threadIdx.x;        // 0..255
    const int q   = tid >> 2;           // sample 0..63
    const int w   = tid & 3;            // lane role: ref word w
    const int n   = b * NSAMP + q;

    // ---- build Peq in SMEM (tid == ref position j) ----
    if (tid == 0) sMinEos = RLEN;
    if (tid < NSAMP) sHlen[tid] = HLEN;
    #pragma unroll
    for (int i = tid; i < SYMS * 4; i += 256) sPeq[i] = 0ull;
    __syncthreads();
    int rt = ref[(size_t)tid * NBATCH + b];
    if (rt == 0) atomicMin(&sMinEos, tid);

    // ---- hyp length scan (coalesced: 64 consecutive seqs per step row) ----
    {
        const int qq = tid & 63;
        #pragma unroll 4
        for (int j = (tid >> 6); j < HLEN; j += 4) {
            int t = hyp[(size_t)j * NSEQ + b * NSAMP + qq];
            if (t == 0) atomicMin(&sHlen[qq], j + 1);
        }
    }
    __syncthreads();
    const int m = (sMinEos < RLEN) ? (sMinEos + 1) : RLEN;  // INCLUDE_EOS
    if (tid < m)
        atomicOr(&sPeq[(rt << 2) + (tid >> 6)], 1ull << (tid & 63));
    __syncthreads();

    const int bsel = (m - 1) >> 6;
    const int pm   = (m - 1) & 63;
    const int hlen = sHlen[q];

    // ---- Myers DP: every lane runs its word; lane bsel owns the score ----
    int sdel;
    if (pm == 63) sdel = quad_run<true >(sPeq, hyp, n, w, pm, hlen);
    else          sdel = quad_run<false>(sPeq, hyp, n, w, pm, hlen);

    if (w == bsel) sEr[q] = (float)(m + sdel) / (float)m;
    __syncthreads();

    // ---- per-batch softmax-weighted centered reduction (warp 0) ----
    if (tid < 32) {
        int lane = tid, base = b * NSAMP;
        float er0 = sEr[lane],         er1 = sEr[lane + 32];
        float lp0 = logp[base + lane], lp1 = logp[base + 32 + lane];

        float mx = fmaxf(lp0, lp1);
        #pragma unroll
        for (int o = 16; o; o >>= 1) mx = fmaxf(mx, __shfl_xor_sync(0xffffffffu, mx, o));

        float e0 = expf(lp0 - mx), e1 = expf(lp1 - mx);
        float se  = e0 + e1;
        float ser = er0 + er1;
        float sep = er0 * e0 + er1 * e1;
        #pragma unroll
        for (int o = 16; o; o >>= 1) {
            se  += __shfl_xor_sync(0xffffffffu, se,  o);
            ser += __shfl_xor_sync(0xffffffffu, ser, o);
            sep += __shfl_xor_sync(0xffffffffu, sep, o);
        }
        if (lane == 0)
            d_partial[b] = (double)sep / (double)se - (double)ser / 64.0;
    }
    __syncthreads();

    // ---- last-block ticket: global mean ----
    if (tid == 0) {
        __threadfence();
        unsigned tk = atomicAdd(&d_ticket, 1u);
        sLast = (tk == NBATCH - 1);
    }
    __syncthreads();
    if (sLast) {
        __threadfence();
        if (tid < NBATCH) sSum[tid] = d_partial[tid];
        __syncthreads();
        #pragma unroll
        for (int o = 64; o; o >>= 1) {
            if (tid < o) sSum[tid] += sSum[tid + o];
            __syncthreads();
        }
        if (tid == 0) {
            out[0] = (float)(sSum[0] / (double)NSEQ);
            d_ticket = 0;               // reset for next graph replay
        }
    }
}

// ---------------------------------------------------------------------------
extern "C" void kernel_launch(void* const* d_in, const int* in_sizes, int n_in,
                              void* d_out, int out_size) {
    const float* logp = (const float*)d_in[0];  // (128,64) f32
    const int*   ref  = (const int*)d_in[1];    // (256,128) i32
    const int*   hyp  = (const int*)d_in[2];    // (256,128,64) i32
    float* out = (float*)d_out;

    mer_loss_kernel<<<NBATCH, 256>>>(hyp, ref, logp, out);
}